// round 14
// baseline (speedup 1.0000x reference)
#include <cuda_runtime.h>
#include <cuda_bf16.h>
#include <cstdint>
#include <math.h>

#define BATCH 256
#define SRCLEN 120
#define TGTLEN 24
#define DIN 216
#define HID 1024
#define KPAD 256

#define KC 128                // K per pipeline chunk
#define NCHUNK_H (HID / KC)   // 8
#define NCHUNK_X (KPAD / KC)  // 2
#define NCHUNK_FULL (NCHUNK_H + NCHUNK_X)   // 10 (decoder)
#define NSTAGE 2

#define AROW 272              // smem row stride bytes (256B data + 16B pad)
#define OFF_AHI 0
#define OFF_ALO 34816
#define OFF_BHI 69632
#define OFF_BLO 87040
#define STAGE_BYTES 104448
#define SMEM_TOTAL (NSTAGE * STAGE_BYTES)   // 208896

// xproj kernel smem layout (A resident, B single-buffered)
#define XP_AHI0 0
#define XP_AHI1 34816
#define XP_ALO0 69632
#define XP_ALO1 104448
#define XP_B    139264        // BHI0,BHI1,BLO0,BLO1 each 17408 -> ends 208896

// ---------------------------------------------------------------------------
// Static device scratch (no runtime allocation allowed)
// ---------------------------------------------------------------------------
__device__ __nv_bfloat16 g_Whh_hi[4096 * HID];
__device__ __nv_bfloat16 g_Whh_lo[4096 * HID];
__device__ __nv_bfloat16 g_Wih_hi[4096 * KPAD];
__device__ __nv_bfloat16 g_Wih_lo[4096 * KPAD];
__device__ __nv_bfloat16 g_Xsrc_hi[SRCLEN * BATCH * KPAD];
__device__ __nv_bfloat16 g_Xsrc_lo[SRCLEN * BATCH * KPAD];
__device__ __nv_bfloat16 g_xdec_hi[BATCH * KPAD];
__device__ __nv_bfloat16 g_xdec_lo[BATCH * KPAD];
__device__ __nv_bfloat16 g_hhi[2][BATCH * HID];
__device__ __nv_bfloat16 g_hlo[2][BATCH * HID];
__device__ float g_hf[BATCH * HID];
__device__ float g_c[BATCH * HID];
__device__ float g_gx[(size_t)SRCLEN * BATCH * 4096];   // precomputed x-gates (+bias)

// ---------------------------------------------------------------------------
// sm_80-safe PTX helpers
// ---------------------------------------------------------------------------
__device__ __forceinline__ uint32_t smem_u32(const void* p) {
    return (uint32_t)__cvta_generic_to_shared(p);
}
__device__ __forceinline__ void cp_async16(uint32_t saddr, const void* gaddr) {
    asm volatile("cp.async.cg.shared.global [%0], [%1], 16;" ::
                 "r"(saddr), "l"(gaddr));
}
__device__ __forceinline__ void cp_commit() {
    asm volatile("cp.async.commit_group;");
}
__device__ __forceinline__ void cp_wait0() {
    asm volatile("cp.async.wait_group 0;");
}
__device__ __forceinline__ void ldmx4(uint32_t addr, uint32_t* r) {
    asm volatile("ldmatrix.sync.aligned.m8n8.x4.shared.b16 {%0,%1,%2,%3}, [%4];"
                 : "=r"(r[0]), "=r"(r[1]), "=r"(r[2]), "=r"(r[3]) : "r"(addr));
}
__device__ __forceinline__ void mma_bf16(float* d, const uint32_t* a,
                                         uint32_t b0, uint32_t b1) {
    asm volatile(
        "mma.sync.aligned.m16n8k16.row.col.f32.bf16.bf16.f32 "
        "{%0,%1,%2,%3}, {%4,%5,%6,%7}, {%8,%9}, {%0,%1,%2,%3};"
        : "+f"(d[0]), "+f"(d[1]), "+f"(d[2]), "+f"(d[3])
        : "r"(a[0]), "r"(a[1]), "r"(a[2]), "r"(a[3]), "r"(b0), "r"(b1));
}

// ---------------------------------------------------------------------------
// Fused LSTM step via bf16-split HMMA (R11 skeleton).
// CTA tile: M=128 ({4 gates} x {32 j}), N=64 batches. Grid (32, 4), 512 thr.
// KC=128, 2 stages, distance-1 prefetch, ONE barrier per chunk.
// nchunk=8 (encoder: h-term only; x-gates from gx) or 10 (decoder: full).
// ---------------------------------------------------------------------------
__global__ __launch_bounds__(512) void lstm_mma_step(
    const __nv_bfloat16* __restrict__ x_hi, const __nv_bfloat16* __restrict__ x_lo,
    const __nv_bfloat16* __restrict__ h_hi_in, const __nv_bfloat16* __restrict__ h_lo_in,
    float* __restrict__ h_out,
    __nv_bfloat16* __restrict__ h_hi_out, __nv_bfloat16* __restrict__ h_lo_out,
    float* __restrict__ c,
    const float* __restrict__ b_ih, const float* __restrict__ b_hh,
    const float* __restrict__ gx, int nchunk)
{
    extern __shared__ __align__(128) char sm[];
    const uint32_t smb = smem_u32(sm);

    const int tid = threadIdx.x;
    const int wid = tid >> 5;
    const int lane = tid & 31;
    const int j0 = blockIdx.x * 32;
    const int b0 = blockIdx.y * 64;

    const int moff = (wid & 3) * 32;   // warp M offset (0..96)
    const int noff = (wid >> 2) * 16;  // warp N offset (0,16,32,48)
    const int rot = ((wid >> 2) + (wid & 3) * 4) & 7;  // k16-group rotation

    float acc0[2][2][4], acc1[2][2][4], acc2[2][2][4];
#pragma unroll
    for (int t = 0; t < 2; t++)
#pragma unroll
        for (int q = 0; q < 2; q++)
#pragma unroll
            for (int i = 0; i < 4; i++) {
                acc0[t][q][i] = 0.f;
                acc1[t][q][i] = 0.f;
                acc2[t][q][i] = 0.f;
            }

    // ---------------- loader (cp.async, 12 x 16B per thread) --------------
    auto issue_loads = [&](int chunk, int stage) {
        const __nv_bfloat16 *Ahi, *Alo, *Bhi, *Blo;
        int ks, k0;
        if (chunk < NCHUNK_H) {
            Ahi = g_Whh_hi; Alo = g_Whh_lo; Bhi = h_hi_in; Blo = h_lo_in;
            ks = HID; k0 = chunk * KC;
        } else {
            Ahi = g_Wih_hi; Alo = g_Wih_lo; Bhi = x_hi; Blo = x_lo;
            ks = KPAD; k0 = (chunk - NCHUNK_H) * KC;
        }
        const uint32_t sbase = smb + stage * STAGE_BYTES;
#pragma unroll
        for (int i = 0; i < 12; i++) {
            int o = tid + i * 512;                // 0..6143
            const __nv_bfloat16* g;
            uint32_t soff;
            if (o < 4096) {                       // A: 128 rows x 16 c16, hi+lo
                int m = o & 2047;
                int r = m >> 4, c16 = m & 15;
                int grow = ((r >> 5) * HID) + j0 + (r & 31);
                g = ((o < 2048) ? Ahi : Alo) + (size_t)grow * ks + k0 + c16 * 8;
                soff = ((o < 2048) ? OFF_AHI : OFF_ALO) + r * AROW + c16 * 16;
            } else {                              // B: 64 rows x 16 c16, hi+lo
                int m = o - 4096;
                int mm = m & 1023;
                int r = mm >> 4, c16 = mm & 15;
                g = ((m < 1024) ? Bhi : Blo) + (size_t)(b0 + r) * ks + k0 + c16 * 8;
                soff = ((m < 1024) ? OFF_BHI : OFF_BLO) + r * AROW + c16 * 16;
            }
            cp_async16(sbase + soff, g);
        }
        cp_commit();
    };

    // ---------------- compute (8 x k16, warp-rotated order) ---------------
    auto compute_chunk = [&](int stage) {
        const uint32_t ab = smb + stage * STAGE_BYTES;
#pragma unroll
        for (int g = 0; g < 8; g++) {
            const int kk = ((g + rot) & 7) * 16;
            const int col = kk + ((lane >> 4) << 3);
            uint32_t a_hi[2][4], a_lo[2][4];
#pragma unroll
            for (int t = 0; t < 2; t++) {
                int row = moff + t * 16 + (lane & 15);
                ldmx4(ab + OFF_AHI + row * AROW + col * 2, a_hi[t]);
                ldmx4(ab + OFF_ALO + row * AROW + col * 2, a_lo[t]);
            }
            uint32_t b_hi[4], b_lo[4];
            {
                int row = noff + (lane & 15);
                ldmx4(ab + OFF_BHI + row * AROW + col * 2, b_hi);
                ldmx4(ab + OFF_BLO + row * AROW + col * 2, b_lo);
            }
#pragma unroll
            for (int t = 0; t < 2; t++)
#pragma unroll
                for (int q = 0; q < 2; q++) {
                    mma_bf16(acc0[t][q], a_hi[t], b_hi[q], b_hi[q + 2]);
                    mma_bf16(acc1[t][q], a_hi[t], b_lo[q], b_lo[q + 2]);
                    mma_bf16(acc2[t][q], a_lo[t], b_hi[q], b_hi[q + 2]);
                }
        }
    };

    // ---------------- 2-stage, distance-1, ONE barrier per chunk ----------
    issue_loads(0, 0);
    for (int i = 0; i < nchunk; i++) {
        cp_wait0();
        __syncthreads();
        if (i + 1 < nchunk) issue_loads(i + 1, (i + 1) & 1);
        compute_chunk(i & 1);
    }

    // ---------------- epilogue: frags -> smem -> LSTM pointwise -----------
    float* Dsm = reinterpret_cast<float*>(sm);    // [128][68] stride
#pragma unroll
    for (int t = 0; t < 2; t++)
#pragma unroll
        for (int q = 0; q < 2; q++) {
            int r0 = moff + t * 16 + (lane >> 2);
            int c0 = noff + q * 8 + (lane & 3) * 2;
#pragma unroll
            for (int i = 0; i < 4; i++) {
                float v = acc0[t][q][i] + acc1[t][q][i] + acc2[t][q][i];
                int rr = r0 + (i >> 1) * 8;
                int cc = c0 + (i & 1);
                Dsm[rr * 68 + cc] = v;
            }
        }
    __syncthreads();

#pragma unroll
    for (int i = 0; i < 4; i++) {
        int id = tid + i * 512;      // 0..2047
        int bb = id >> 5;            // 0..63
        int jj = id & 31;
        int b = b0 + bb;
        int jg = j0 + jj;
        float e0, e1, e2, e3;
        if (gx) {                    // precomputed x-gates incl. biases
            const float* gb = gx + (size_t)b * 4096;
            e0 = gb[jg]; e1 = gb[HID + jg]; e2 = gb[2*HID + jg]; e3 = gb[3*HID + jg];
        } else {
            e0 = b_ih[jg]         + b_hh[jg];
            e1 = b_ih[HID + jg]   + b_hh[HID + jg];
            e2 = b_ih[2*HID + jg] + b_hh[2*HID + jg];
            e3 = b_ih[3*HID + jg] + b_hh[3*HID + jg];
        }
        float gi = Dsm[(0   + jj) * 68 + bb] + e0;
        float gf = Dsm[(32  + jj) * 68 + bb] + e1;
        float gg = Dsm[(64  + jj) * 68 + bb] + e2;
        float go = Dsm[(96  + jj) * 68 + bb] + e3;
        float iv = 1.f / (1.f + expf(-gi));
        float fv = 1.f / (1.f + expf(-gf));
        float gv = tanhf(gg);
        float ov = 1.f / (1.f + expf(-go));
        size_t idx = (size_t)b * HID + jg;
        float cn = fv * c[idx] + iv * gv;
        c[idx] = cn;
        float hv = ov * tanhf(cn);
        h_out[idx] = hv;
        __nv_bfloat16 hh = __float2bfloat16(hv);
        h_hi_out[idx] = hh;
        h_lo_out[idx] = __float2bfloat16(hv - __bfloat162float(hh));
    }
}

// ---------------------------------------------------------------------------
// Encoder x-projection precompute: gx[s][b][4H] = src[s,b,:]@W_ih^T + biases.
// Grid (32, 4), 512 thr. A (W_ih tile, 4 slabs) resident in smem; per step
// stream B (69.6KB), compute 2 K-chunks, stage via Dsm, write gx.
// ---------------------------------------------------------------------------
__global__ __launch_bounds__(512) void xproj_kernel(
    const float* __restrict__ b_ih, const float* __restrict__ b_hh,
    float* __restrict__ gx)
{
    extern __shared__ __align__(128) char sm[];
    const uint32_t smb = smem_u32(sm);

    const int tid = threadIdx.x;
    const int wid = tid >> 5;
    const int lane = tid & 31;
    const int j0 = blockIdx.x * 32;
    const int b0 = blockIdx.y * 64;

    const int moff = (wid & 3) * 32;
    const int noff = (wid >> 2) * 16;
    const int rot = ((wid >> 2) + (wid & 3) * 4) & 7;

    // ---- load A (W_ih hi/lo, 2 K-chunks) once: 8192 x 16B ----
#pragma unroll
    for (int i = 0; i < 16; i++) {
        int o = tid + i * 512;            // 0..8191
        int slab = o >> 11;               // 0..3: hi-k0, hi-k1, lo-k0, lo-k1
        int m = o & 2047;
        int r = m >> 4, c16 = m & 15;
        int grow = ((r >> 5) * HID) + j0 + (r & 31);
        const __nv_bfloat16* g = ((slab < 2) ? g_Wih_hi : g_Wih_lo)
                                 + (size_t)grow * KPAD + (slab & 1) * 128 + c16 * 8;
        cp_async16(smb + XP_AHI0 + slab * 34816 + r * AROW + c16 * 16, g);
    }

    // ---- B loader for step s: 4096 x 16B ----
    auto issue_B = [&](int s) {
#pragma unroll
        for (int i = 0; i < 8; i++) {
            int o = tid + i * 512;        // 0..4095
            int slab = o >> 10;           // hi-k0, hi-k1, lo-k0, lo-k1
            int m = o & 1023;
            int r = m >> 4, c16 = m & 15;
            const __nv_bfloat16* g = ((slab < 2) ? g_Xsrc_hi : g_Xsrc_lo)
                + ((size_t)s * BATCH + b0 + r) * KPAD + (slab & 1) * 128 + c16 * 8;
            cp_async16(smb + XP_B + slab * 17408 + r * AROW + c16 * 16, g);
        }
        cp_commit();
    };

    issue_B(0);   // commits A + B(0) together

    float* Dsm = reinterpret_cast<float*>(sm + XP_B);   // overlays BHI0+BHI1

    for (int s = 0; s < SRCLEN; s++) {
        cp_wait0();
        __syncthreads();

        float acc0[2][2][4], acc1[2][2][4], acc2[2][2][4];
#pragma unroll
        for (int t = 0; t < 2; t++)
#pragma unroll
            for (int q = 0; q < 2; q++)
#pragma unroll
                for (int i = 0; i < 4; i++) {
                    acc0[t][q][i] = 0.f; acc1[t][q][i] = 0.f; acc2[t][q][i] = 0.f;
                }

#pragma unroll
        for (int chunk = 0; chunk < 2; chunk++) {
            const uint32_t aHI = smb + XP_AHI0 + chunk * 34816;
            const uint32_t aLO = smb + XP_ALO0 + chunk * 34816;
            const uint32_t bHI = smb + XP_B + chunk * 17408;
            const uint32_t bLO = smb + XP_B + 34816 + chunk * 17408;
#pragma unroll
            for (int g = 0; g < 8; g++) {
                const int kk = ((g + rot) & 7) * 16;
                const int col = kk + ((lane >> 4) << 3);
                uint32_t a_hi[2][4], a_lo[2][4];
#pragma unroll
                for (int t = 0; t < 2; t++) {
                    int row = moff + t * 16 + (lane & 15);
                    ldmx4(aHI + row * AROW + col * 2, a_hi[t]);
                    ldmx4(aLO + row * AROW + col * 2, a_lo[t]);
                }
                uint32_t b_hi[4], b_lo[4];
                {
                    int row = noff + (lane & 15);
                    ldmx4(bHI + row * AROW + col * 2, b_hi);
                    ldmx4(bLO + row * AROW + col * 2, b_lo);
                }
#pragma unroll
                for (int t = 0; t < 2; t++)
#pragma unroll
                    for (int q = 0; q < 2; q++) {
                        mma_bf16(acc0[t][q], a_hi[t], b_hi[q], b_hi[q + 2]);
                        mma_bf16(acc1[t][q], a_hi[t], b_lo[q], b_lo[q + 2]);
                        mma_bf16(acc2[t][q], a_lo[t], b_hi[q], b_hi[q + 2]);
                    }
            }
        }
        __syncthreads();   // all B reads done -> Dsm (B region) writable

#pragma unroll
        for (int t = 0; t < 2; t++)
#pragma unroll
            for (int q = 0; q < 2; q++) {
                int r0 = moff + t * 16 + (lane >> 2);
                int c0 = noff + q * 8 + (lane & 3) * 2;
#pragma unroll
                for (int i = 0; i < 4; i++) {
                    float v = acc0[t][q][i] + acc1[t][q][i] + acc2[t][q][i];
                    Dsm[(r0 + (i >> 1) * 8) * 68 + c0 + (i & 1)] = v;
                }
            }
        __syncthreads();

#pragma unroll
        for (int i = 0; i < 4; i++) {
            int id = tid + i * 512;
            int bb = id >> 5;
            int jj = id & 31;
            int jg = j0 + jj;
            float* dst = gx + ((size_t)s * BATCH + b0 + bb) * 4096;
#pragma unroll
            for (int g = 0; g < 4; g++) {
                float v = Dsm[(g * 32 + jj) * 68 + bb]
                        + b_ih[g * HID + jg] + b_hh[g * HID + jg];
                dst[g * HID + jg] = v;
            }
        }
        __syncthreads();   // Dsm reads done -> B region reusable

        if (s + 1 < SRCLEN) issue_B(s + 1);
    }
}

// ---------------------------------------------------------------------------
// Conversion kernels
// ---------------------------------------------------------------------------
__global__ void split_mat_kernel(const float* __restrict__ src,
                                 __nv_bfloat16* __restrict__ hi,
                                 __nv_bfloat16* __restrict__ lo, int n) {
    int i = blockIdx.x * blockDim.x + threadIdx.x;
    if (i < n) {
        float v = src[i];
        __nv_bfloat16 h = __float2bfloat16(v);
        hi[i] = h;
        lo[i] = __float2bfloat16(v - __bfloat162float(h));
    }
}

__global__ void split_pad_kernel(const float* __restrict__ src, int srcStride, int srcK,
                                 __nv_bfloat16* __restrict__ hi,
                                 __nv_bfloat16* __restrict__ lo, int rows, int dstK) {
    int i = blockIdx.x * blockDim.x + threadIdx.x;
    if (i < rows * dstK) {
        int r = i / dstK, k = i % dstK;
        float v = (k < srcK) ? src[(size_t)r * srcStride + k] : 0.f;
        __nv_bfloat16 h = __float2bfloat16(v);
        hi[i] = h;
        lo[i] = __float2bfloat16(v - __bfloat162float(h));
    }
}

__global__ void split_src_kernel(const float* __restrict__ src,
                                 __nv_bfloat16* __restrict__ hi,
                                 __nv_bfloat16* __restrict__ lo) {
    int i = blockIdx.x * blockDim.x + threadIdx.x;
    if (i < SRCLEN * BATCH * KPAD) {
        int k = i & (KPAD - 1);
        int sb = i >> 8;
        int b = sb & (BATCH - 1);
        int s = sb >> 8;
        float v = (k < DIN) ? src[((size_t)b * SRCLEN + s) * DIN + k] : 0.f;
        __nv_bfloat16 h = __float2bfloat16(v);
        hi[i] = h;
        lo[i] = __float2bfloat16(v - __bfloat162float(h));
    }
}

// ---------------------------------------------------------------------------
// Output projection fused with feedback split.
// ---------------------------------------------------------------------------
__global__ __launch_bounds__(256) void out_proj_kernel(
    const float* __restrict__ h,
    const float* __restrict__ W_out,
    const float* __restrict__ b_out,
    float* __restrict__ out, int out_stride,
    __nv_bfloat16* __restrict__ xd_hi, __nv_bfloat16* __restrict__ xd_lo)
{
    __shared__ float Hs[16][17];
    __shared__ float Wo[16][17];

    const int tid = threadIdx.x;
    const int txd = tid & 15;
    const int tyb = tid >> 4;
    const int d0 = blockIdx.x * 16;
    const int b0 = blockIdx.y * 16;

    float acc = 0.f;
    for (int k0 = 0; k0 < HID; k0 += 16) {
        __syncthreads();
        Hs[txd][tyb] = h[(size_t)(b0 + tyb) * HID + k0 + txd];
        Wo[txd][tyb] = (d0 + tyb < DIN)
            ? W_out[(size_t)(d0 + tyb) * HID + k0 + txd] : 0.f;
        __syncthreads();
#pragma unroll
        for (int k = 0; k < 16; k++)
            acc += Hs[k][tyb] * Wo[k][txd];
    }
    if (d0 + txd < DIN) {
        float v = acc + b_out[d0 + txd];
        out[(size_t)(b0 + tyb) * out_stride + d0 + txd] = v;
        if (xd_hi) {
            size_t xi = (size_t)(b0 + tyb) * KPAD + d0 + txd;
            __nv_bfloat16 hh = __float2bfloat16(v);
            xd_hi[xi] = hh;
            xd_lo[xi] = __float2bfloat16(v - __bfloat162float(hh));
        }
    }
}

// ---------------------------------------------------------------------------
extern "C" void kernel_launch(void* const* d_in, const int* in_sizes, int n_in,
                              void* d_out, int out_size)
{
    const float* src   = (const float*)d_in[0];
    const float* W_ih  = (const float*)d_in[2];
    const float* W_hh  = (const float*)d_in[3];
    const float* b_ih  = (const float*)d_in[4];
    const float* b_hh  = (const float*)d_in[5];
    const float* W_out = (const float*)d_in[6];
    const float* b_out = (const float*)d_in[7];
    float* out = (float*)d_out;

    static bool attr_set = false;
    if (!attr_set) {
        cudaFuncSetAttribute(lstm_mma_step,
                             cudaFuncAttributeMaxDynamicSharedMemorySize, SMEM_TOTAL);
        cudaFuncSetAttribute(xproj_kernel,
                             cudaFuncAttributeMaxDynamicSharedMemorySize, SMEM_TOTAL);
        attr_set = true;
    }

    __nv_bfloat16 *Whh_hi, *Wih_hi, *Xs_hi, *Xs_lo, *xd_hi, *xd_lo, *hhi, *hlo;
    __nv_bfloat16 *Whh_lo, *Wih_lo;
    float *hf, *cc, *gx;
    cudaGetSymbolAddress((void**)&Whh_hi, g_Whh_hi);
    cudaGetSymbolAddress((void**)&Whh_lo, g_Whh_lo);
    cudaGetSymbolAddress((void**)&Wih_hi, g_Wih_hi);
    cudaGetSymbolAddress((void**)&Wih_lo, g_Wih_lo);
    cudaGetSymbolAddress((void**)&Xs_hi, g_Xsrc_hi);
    cudaGetSymbolAddress((void**)&Xs_lo, g_Xsrc_lo);
    cudaGetSymbolAddress((void**)&xd_hi, g_xdec_hi);
    cudaGetSymbolAddress((void**)&xd_lo, g_xdec_lo);
    cudaGetSymbolAddress((void**)&hhi, g_hhi);
    cudaGetSymbolAddress((void**)&hlo, g_hlo);
    cudaGetSymbolAddress((void**)&hf, g_hf);
    cudaGetSymbolAddress((void**)&cc, g_c);
    cudaGetSymbolAddress((void**)&gx, g_gx);
    __nv_bfloat16* hhb[2] = {hhi, hhi + BATCH * HID};
    __nv_bfloat16* hlb[2] = {hlo, hlo + BATCH * HID};

    cudaMemsetAsync(hhb[0], 0, (size_t)BATCH * HID * sizeof(__nv_bfloat16));
    cudaMemsetAsync(hlb[0], 0, (size_t)BATCH * HID * sizeof(__nv_bfloat16));
    cudaMemsetAsync(cc, 0, (size_t)BATCH * HID * sizeof(float));
    cudaMemsetAsync(xd_hi, 0, (size_t)BATCH * KPAD * sizeof(__nv_bfloat16));
    cudaMemsetAsync(xd_lo, 0, (size_t)BATCH * KPAD * sizeof(__nv_bfloat16));

    {
        int n = 4096 * HID;
        split_mat_kernel<<<(n + 255) / 256, 256>>>(W_hh, Whh_hi, Whh_lo, n);
        split_pad_kernel<<<(4096 * KPAD + 255) / 256, 256>>>(W_ih, DIN, DIN,
                                                             Wih_hi, Wih_lo, 4096, KPAD);
        int m = SRCLEN * BATCH * KPAD;
        split_src_kernel<<<(m + 255) / 256, 256>>>(src, Xs_hi, Xs_lo);
    }

    dim3 grid(32, 4);
    dim3 pgrid(14, 16);

    // Precompute encoder x-gates (parallel, off the sequential path)
    xproj_kernel<<<grid, 512, SMEM_TOTAL>>>(b_ih, b_hh, gx);

    int cur = 0;

    // Encoder: K=1024 (8 chunks), x-gates from gx
    for (int s = 0; s < SRCLEN; s++) {
        lstm_mma_step<<<grid, 512, SMEM_TOTAL>>>(
            nullptr, nullptr,
            hhb[cur], hlb[cur], hf, hhb[1 - cur], hlb[1 - cur], cc, b_ih, b_hh,
            gx + (size_t)s * BATCH * 4096, NCHUNK_H);
        cur ^= 1;
    }

    // Decoder: full K=1280 (10 chunks), bias path
    const __nv_bfloat16* x_hi = Xs_hi + (size_t)(SRCLEN - 1) * BATCH * KPAD;
    const __nv_bfloat16* x_lo = Xs_lo + (size_t)(SRCLEN - 1) * BATCH * KPAD;
    for (int t = 0; t < TGTLEN; t++) {
        lstm_mma_step<<<grid, 512, SMEM_TOTAL>>>(
            x_hi, x_lo, hhb[cur], hlb[cur], hf, hhb[1 - cur], hlb[1 - cur],
            cc, b_ih, b_hh, nullptr, NCHUNK_FULL);
        cur ^= 1;
        bool feed = (t + 1 < TGTLEN);
        out_proj_kernel<<<pgrid, 256>>>(hf, W_out, b_out,
                                        out + (size_t)t * DIN, TGTLEN * DIN,
                                        feed ? xd_hi : nullptr,
                                        feed ? xd_lo : nullptr);
        x_hi = xd_hi;
        x_lo = xd_lo;
    }
}

// round 15
// speedup vs baseline: 1.0602x; 1.0602x over previous
#include <cuda_runtime.h>
#include <cuda_bf16.h>
#include <cstdint>
#include <math.h>

#define BATCH 256
#define SRCLEN 120
#define TGTLEN 24
#define DIN 216
#define HID 1024
#define KPAD 256

#define KC 128                // K per pipeline chunk
#define NCHUNK_H (HID / KC)   // 8
#define NCHUNK_X (KPAD / KC)  // 2
#define NCHUNK (NCHUNK_H + NCHUNK_X)   // 10
#define NSTAGE 2

#define AROW 272              // smem row stride bytes (256B data + 16B pad)
#define OFF_AHI 0
#define OFF_ALO 34816
#define OFF_BHI 69632
#define OFF_BLO 87040
#define STAGE_BYTES 104448
#define SMEM_TOTAL (NSTAGE * STAGE_BYTES)   // 208896

// ---------------------------------------------------------------------------
// Static device scratch (no runtime allocation allowed)
// ---------------------------------------------------------------------------
__device__ __nv_bfloat16 g_Whh_hi[4096 * HID];
__device__ __nv_bfloat16 g_Whh_lo[4096 * HID];
__device__ __nv_bfloat16 g_Wih_hi[4096 * KPAD];
__device__ __nv_bfloat16 g_Wih_lo[4096 * KPAD];
__device__ __nv_bfloat16 g_Xsrc_hi[SRCLEN * BATCH * KPAD];
__device__ __nv_bfloat16 g_Xsrc_lo[SRCLEN * BATCH * KPAD];
__device__ __nv_bfloat16 g_xdec_hi[BATCH * KPAD];
__device__ __nv_bfloat16 g_xdec_lo[BATCH * KPAD];
__device__ __nv_bfloat16 g_hhi[2][BATCH * HID];
__device__ __nv_bfloat16 g_hlo[2][BATCH * HID];
__device__ float g_hf[BATCH * HID];
__device__ float g_c[BATCH * HID];
__device__ float g_bsum[4096];       // b_ih + b_hh pre-summed

// ---------------------------------------------------------------------------
// sm_80-safe PTX helpers
// ---------------------------------------------------------------------------
__device__ __forceinline__ uint32_t smem_u32(const void* p) {
    return (uint32_t)__cvta_generic_to_shared(p);
}
__device__ __forceinline__ void cp_async16(uint32_t saddr, const void* gaddr) {
    asm volatile("cp.async.cg.shared.global [%0], [%1], 16;" ::
                 "r"(saddr), "l"(gaddr));
}
__device__ __forceinline__ void cp_commit() {
    asm volatile("cp.async.commit_group;");
}
__device__ __forceinline__ void cp_wait0() {
    asm volatile("cp.async.wait_group 0;");
}
__device__ __forceinline__ void ldmx4(uint32_t addr, uint32_t* r) {
    asm volatile("ldmatrix.sync.aligned.m8n8.x4.shared.b16 {%0,%1,%2,%3}, [%4];"
                 : "=r"(r[0]), "=r"(r[1]), "=r"(r[2]), "=r"(r[3]) : "r"(addr));
}
__device__ __forceinline__ void mma_bf16(float* d, const uint32_t* a,
                                         uint32_t b0, uint32_t b1) {
    asm volatile(
        "mma.sync.aligned.m16n8k16.row.col.f32.bf16.bf16.f32 "
        "{%0,%1,%2,%3}, {%4,%5,%6,%7}, {%8,%9}, {%0,%1,%2,%3};"
        : "+f"(d[0]), "+f"(d[1]), "+f"(d[2]), "+f"(d[3])
        : "r"(a[0]), "r"(a[1]), "r"(a[2]), "r"(a[3]), "r"(b0), "r"(b1));
}

// ---------------------------------------------------------------------------
// Fused LSTM step via bf16-split HMMA (R11 skeleton + deferred prefetch).
// CTA tile: M=128 ({4 gates} x {32 j}), N=64 batches. Grid (32, 4), 512 thr.
// KC=128, 2 stages, distance-1 prefetch, ONE barrier per chunk; the i+1
// prefetch is issued AFTER the first 2 k16 groups so the critical ldmatrix
// reads hit the LSU first. h_out (fp32) written only when non-null.
// ---------------------------------------------------------------------------
__global__ __launch_bounds__(512) void lstm_mma_step(
    const __nv_bfloat16* __restrict__ x_hi, const __nv_bfloat16* __restrict__ x_lo,
    const __nv_bfloat16* __restrict__ h_hi_in, const __nv_bfloat16* __restrict__ h_lo_in,
    float* __restrict__ h_out,
    __nv_bfloat16* __restrict__ h_hi_out, __nv_bfloat16* __restrict__ h_lo_out,
    float* __restrict__ c)
{
    extern __shared__ __align__(128) char sm[];
    const uint32_t smb = smem_u32(sm);

    const int tid = threadIdx.x;
    const int wid = tid >> 5;
    const int lane = tid & 31;
    const int j0 = blockIdx.x * 32;
    const int b0 = blockIdx.y * 64;

    const int moff = (wid & 3) * 32;   // warp M offset (0..96)
    const int noff = (wid >> 2) * 16;  // warp N offset (0,16,32,48)
    const int rot = ((wid >> 2) + (wid & 3) * 4) & 7;  // k16-group rotation

    float acc0[2][2][4], acc1[2][2][4], acc2[2][2][4];
#pragma unroll
    for (int t = 0; t < 2; t++)
#pragma unroll
        for (int q = 0; q < 2; q++)
#pragma unroll
            for (int i = 0; i < 4; i++) {
                acc0[t][q][i] = 0.f;
                acc1[t][q][i] = 0.f;
                acc2[t][q][i] = 0.f;
            }

    // ---------------- loader (cp.async, 12 x 16B per thread) --------------
    auto issue_loads = [&](int chunk, int stage) {
        const __nv_bfloat16 *Ahi, *Alo, *Bhi, *Blo;
        int ks, k0;
        if (chunk < NCHUNK_H) {
            Ahi = g_Whh_hi; Alo = g_Whh_lo; Bhi = h_hi_in; Blo = h_lo_in;
            ks = HID; k0 = chunk * KC;
        } else {
            Ahi = g_Wih_hi; Alo = g_Wih_lo; Bhi = x_hi; Blo = x_lo;
            ks = KPAD; k0 = (chunk - NCHUNK_H) * KC;
        }
        const uint32_t sbase = smb + stage * STAGE_BYTES;
#pragma unroll
        for (int i = 0; i < 12; i++) {
            int o = tid + i * 512;                // 0..6143
            const __nv_bfloat16* g;
            uint32_t soff;
            if (o < 4096) {                       // A: 128 rows x 16 c16, hi+lo
                int m = o & 2047;
                int r = m >> 4, c16 = m & 15;
                int grow = ((r >> 5) * HID) + j0 + (r & 31);
                g = ((o < 2048) ? Ahi : Alo) + (size_t)grow * ks + k0 + c16 * 8;
                soff = ((o < 2048) ? OFF_AHI : OFF_ALO) + r * AROW + c16 * 16;
            } else {                              // B: 64 rows x 16 c16, hi+lo
                int m = o - 4096;
                int mm = m & 1023;
                int r = mm >> 4, c16 = mm & 15;
                g = ((m < 1024) ? Bhi : Blo) + (size_t)(b0 + r) * ks + k0 + c16 * 8;
                soff = ((m < 1024) ? OFF_BHI : OFF_BLO) + r * AROW + c16 * 16;
            }
            cp_async16(sbase + soff, g);
        }
        cp_commit();
    };

    // ---------------- compute a range of k16 groups -----------------------
    auto compute_range = [&](int stage, int g_lo, int g_hi) {
        const uint32_t ab = smb + stage * STAGE_BYTES;
#pragma unroll
        for (int g = g_lo; g < g_hi; g++) {
            const int kk = ((g + rot) & 7) * 16;
            const int col = kk + ((lane >> 4) << 3);   // ldmatrix column (halfs)
            uint32_t a_hi[2][4], a_lo[2][4];
#pragma unroll
            for (int t = 0; t < 2; t++) {
                int row = moff + t * 16 + (lane & 15);
                ldmx4(ab + OFF_AHI + row * AROW + col * 2, a_hi[t]);
                ldmx4(ab + OFF_ALO + row * AROW + col * 2, a_lo[t]);
            }
            uint32_t b_hi[4], b_lo[4];
            {
                int row = noff + (lane & 15);
                ldmx4(ab + OFF_BHI + row * AROW + col * 2, b_hi);
                ldmx4(ab + OFF_BLO + row * AROW + col * 2, b_lo);
            }
#pragma unroll
            for (int t = 0; t < 2; t++)
#pragma unroll
                for (int q = 0; q < 2; q++) {
                    mma_bf16(acc0[t][q], a_hi[t], b_hi[q], b_hi[q + 2]);
                    mma_bf16(acc1[t][q], a_hi[t], b_lo[q], b_lo[q + 2]);
                    mma_bf16(acc2[t][q], a_lo[t], b_hi[q], b_hi[q + 2]);
                }
        }
    };

    // ---------------- 2-stage, distance-1, ONE barrier per chunk ----------
    // iter i: cp_wait0 -> __syncthreads (publishes chunk-i writes; licenses
    // overwriting stage (i-1)&1) -> compute groups 0-1 (critical LDSMs hit
    // the LSU first) -> issue(i+1 -> stage (i+1)&1) -> compute groups 2-7.
    issue_loads(0, 0);
    for (int i = 0; i < NCHUNK; i++) {
        cp_wait0();
        __syncthreads();
        compute_range(i & 1, 0, 2);
        if (i + 1 < NCHUNK) issue_loads(i + 1, (i + 1) & 1);
        compute_range(i & 1, 2, 8);
    }

    // ---------------- epilogue: frags -> smem -> LSTM pointwise -----------
    float* Dsm = reinterpret_cast<float*>(sm);    // [128][68] stride
#pragma unroll
    for (int t = 0; t < 2; t++)
#pragma unroll
        for (int q = 0; q < 2; q++) {
            int r0 = moff + t * 16 + (lane >> 2);
            int c0 = noff + q * 8 + (lane & 3) * 2;
#pragma unroll
            for (int i = 0; i < 4; i++) {
                float v = acc0[t][q][i] + acc1[t][q][i] + acc2[t][q][i];
                int rr = r0 + (i >> 1) * 8;
                int cc = c0 + (i & 1);
                Dsm[rr * 68 + cc] = v;
            }
        }
    __syncthreads();

#pragma unroll
    for (int i = 0; i < 4; i++) {
        int id = tid + i * 512;      // 0..2047
        int bb = id >> 5;            // 0..63
        int jj = id & 31;
        int b = b0 + bb;
        int jg = j0 + jj;
        float gi = Dsm[(0   + jj) * 68 + bb] + g_bsum[jg];
        float gf = Dsm[(32  + jj) * 68 + bb] + g_bsum[HID + jg];
        float gg = Dsm[(64  + jj) * 68 + bb] + g_bsum[2*HID + jg];
        float go = Dsm[(96  + jj) * 68 + bb] + g_bsum[3*HID + jg];
        float iv = 1.f / (1.f + expf(-gi));
        float fv = 1.f / (1.f + expf(-gf));
        float gv = tanhf(gg);
        float ov = 1.f / (1.f + expf(-go));
        size_t idx = (size_t)b * HID + jg;
        float cn = fv * c[idx] + iv * gv;
        c[idx] = cn;
        float hv = ov * tanhf(cn);
        if (h_out) h_out[idx] = hv;
        __nv_bfloat16 hh = __float2bfloat16(hv);
        h_hi_out[idx] = hh;
        h_lo_out[idx] = __float2bfloat16(hv - __bfloat162float(hh));
    }
}

// ---------------------------------------------------------------------------
// Conversion kernels
// ---------------------------------------------------------------------------
__global__ void split_mat_kernel(const float* __restrict__ src,
                                 __nv_bfloat16* __restrict__ hi,
                                 __nv_bfloat16* __restrict__ lo, int n) {
    int i = blockIdx.x * blockDim.x + threadIdx.x;
    if (i < n) {
        float v = src[i];
        __nv_bfloat16 h = __float2bfloat16(v);
        hi[i] = h;
        lo[i] = __float2bfloat16(v - __bfloat162float(h));
    }
}

__global__ void split_pad_kernel(const float* __restrict__ src, int srcStride, int srcK,
                                 __nv_bfloat16* __restrict__ hi,
                                 __nv_bfloat16* __restrict__ lo, int rows, int dstK) {
    int i = blockIdx.x * blockDim.x + threadIdx.x;
    if (i < rows * dstK) {
        int r = i / dstK, k = i % dstK;
        float v = (k < srcK) ? src[(size_t)r * srcStride + k] : 0.f;
        __nv_bfloat16 h = __float2bfloat16(v);
        hi[i] = h;
        lo[i] = __float2bfloat16(v - __bfloat162float(h));
    }
}

__global__ void split_src_kernel(const float* __restrict__ src,
                                 __nv_bfloat16* __restrict__ hi,
                                 __nv_bfloat16* __restrict__ lo) {
    int i = blockIdx.x * blockDim.x + threadIdx.x;
    if (i < SRCLEN * BATCH * KPAD) {
        int k = i & (KPAD - 1);
        int sb = i >> 8;
        int b = sb & (BATCH - 1);
        int s = sb >> 8;
        float v = (k < DIN) ? src[((size_t)b * SRCLEN + s) * DIN + k] : 0.f;
        __nv_bfloat16 h = __float2bfloat16(v);
        hi[i] = h;
        lo[i] = __float2bfloat16(v - __bfloat162float(h));
    }
}

__global__ void bias_sum_kernel(const float* __restrict__ b_ih,
                                const float* __restrict__ b_hh,
                                float* __restrict__ bsum) {
    int i = blockIdx.x * blockDim.x + threadIdx.x;
    if (i < 4096) bsum[i] = b_ih[i] + b_hh[i];
}

// ---------------------------------------------------------------------------
// Output projection fused with feedback split:
// out[b,d] = h[b,:] @ W_out[d,:] + b_out[d]; also writes xd hi/lo (d < DIN).
// ---------------------------------------------------------------------------
__global__ __launch_bounds__(256) void out_proj_kernel(
    const float* __restrict__ h,
    const float* __restrict__ W_out,
    const float* __restrict__ b_out,
    float* __restrict__ out, int out_stride,
    __nv_bfloat16* __restrict__ xd_hi, __nv_bfloat16* __restrict__ xd_lo)
{
    __shared__ float Hs[16][17];
    __shared__ float Wo[16][17];

    const int tid = threadIdx.x;
    const int txd = tid & 15;
    const int tyb = tid >> 4;
    const int d0 = blockIdx.x * 16;
    const int b0 = blockIdx.y * 16;

    float acc = 0.f;
    for (int k0 = 0; k0 < HID; k0 += 16) {
        __syncthreads();
        Hs[txd][tyb] = h[(size_t)(b0 + tyb) * HID + k0 + txd];
        Wo[txd][tyb] = (d0 + tyb < DIN)
            ? W_out[(size_t)(d0 + tyb) * HID + k0 + txd] : 0.f;
        __syncthreads();
#pragma unroll
        for (int k = 0; k < 16; k++)
            acc += Hs[k][tyb] * Wo[k][txd];
    }
    if (d0 + txd < DIN) {
        float v = acc + b_out[d0 + txd];
        out[(size_t)(b0 + tyb) * out_stride + d0 + txd] = v;
        if (xd_hi) {
            size_t xi = (size_t)(b0 + tyb) * KPAD + d0 + txd;
            __nv_bfloat16 hh = __float2bfloat16(v);
            xd_hi[xi] = hh;
            xd_lo[xi] = __float2bfloat16(v - __bfloat162float(hh));
        }
    }
}

// ---------------------------------------------------------------------------
extern "C" void kernel_launch(void* const* d_in, const int* in_sizes, int n_in,
                              void* d_out, int out_size)
{
    const float* src   = (const float*)d_in[0];
    const float* W_ih  = (const float*)d_in[2];
    const float* W_hh  = (const float*)d_in[3];
    const float* b_ih  = (const float*)d_in[4];
    const float* b_hh  = (const float*)d_in[5];
    const float* W_out = (const float*)d_in[6];
    const float* b_out = (const float*)d_in[7];
    float* out = (float*)d_out;

    static bool attr_set = false;
    if (!attr_set) {
        cudaFuncSetAttribute(lstm_mma_step,
                             cudaFuncAttributeMaxDynamicSharedMemorySize, SMEM_TOTAL);
        attr_set = true;
    }

    __nv_bfloat16 *Whh_hi, *Wih_hi, *Xs_hi, *Xs_lo, *xd_hi, *xd_lo, *hhi, *hlo;
    __nv_bfloat16 *Whh_lo, *Wih_lo;
    float *hf, *cc, *bsum;
    cudaGetSymbolAddress((void**)&Whh_hi, g_Whh_hi);
    cudaGetSymbolAddress((void**)&Whh_lo, g_Whh_lo);
    cudaGetSymbolAddress((void**)&Wih_hi, g_Wih_hi);
    cudaGetSymbolAddress((void**)&Wih_lo, g_Wih_lo);
    cudaGetSymbolAddress((void**)&Xs_hi, g_Xsrc_hi);
    cudaGetSymbolAddress((void**)&Xs_lo, g_Xsrc_lo);
    cudaGetSymbolAddress((void**)&xd_hi, g_xdec_hi);
    cudaGetSymbolAddress((void**)&xd_lo, g_xdec_lo);
    cudaGetSymbolAddress((void**)&hhi, g_hhi);
    cudaGetSymbolAddress((void**)&hlo, g_hlo);
    cudaGetSymbolAddress((void**)&hf, g_hf);
    cudaGetSymbolAddress((void**)&cc, g_c);
    cudaGetSymbolAddress((void**)&bsum, g_bsum);
    __nv_bfloat16* hhb[2] = {hhi, hhi + BATCH * HID};
    __nv_bfloat16* hlb[2] = {hlo, hlo + BATCH * HID};

    cudaMemsetAsync(hhb[0], 0, (size_t)BATCH * HID * sizeof(__nv_bfloat16));
    cudaMemsetAsync(hlb[0], 0, (size_t)BATCH * HID * sizeof(__nv_bfloat16));
    cudaMemsetAsync(cc, 0, (size_t)BATCH * HID * sizeof(float));
    cudaMemsetAsync(xd_hi, 0, (size_t)BATCH * KPAD * sizeof(__nv_bfloat16));
    cudaMemsetAsync(xd_lo, 0, (size_t)BATCH * KPAD * sizeof(__nv_bfloat16));

    {
        int n = 4096 * HID;
        split_mat_kernel<<<(n + 255) / 256, 256>>>(W_hh, Whh_hi, Whh_lo, n);
        split_pad_kernel<<<(4096 * KPAD + 255) / 256, 256>>>(W_ih, DIN, DIN,
                                                             Wih_hi, Wih_lo, 4096, KPAD);
        int m = SRCLEN * BATCH * KPAD;
        split_src_kernel<<<(m + 255) / 256, 256>>>(src, Xs_hi, Xs_lo);
        bias_sum_kernel<<<16, 256>>>(b_ih, b_hh, bsum);
    }

    dim3 grid(32, 4);
    dim3 pgrid(14, 16);
    int cur = 0;

    // Encoder (no fp32 h needed)
    for (int s = 0; s < SRCLEN; s++) {
        lstm_mma_step<<<grid, 512, SMEM_TOTAL>>>(
            Xs_hi + (size_t)s * BATCH * KPAD, Xs_lo + (size_t)s * BATCH * KPAD,
            hhb[cur], hlb[cur], nullptr, hhb[1 - cur], hlb[1 - cur], cc);
        cur ^= 1;
    }

    // Decoder
    const __nv_bfloat16* x_hi = Xs_hi + (size_t)(SRCLEN - 1) * BATCH * KPAD;
    const __nv_bfloat16* x_lo = Xs_lo + (size_t)(SRCLEN - 1) * BATCH * KPAD;
    for (int t = 0; t < TGTLEN; t++) {
        lstm_mma_step<<<grid, 512, SMEM_TOTAL>>>(
            x_hi, x_lo, hhb[cur], hlb[cur], hf, hhb[1 - cur], hlb[1 - cur], cc);
        cur ^= 1;
        bool feed = (t + 1 < TGTLEN);
        out_proj_kernel<<<pgrid, 256>>>(hf, W_out, b_out,
                                        out + (size_t)t * DIN, TGTLEN * DIN,
                                        feed ? xd_hi : nullptr,
                                        feed ? xd_lo : nullptr);
        x_hi = xd_hi;
        x_lo = xd_lo;
    }
}

// round 16
// speedup vs baseline: 1.0758x; 1.0147x over previous
#include <cuda_runtime.h>
#include <cuda_bf16.h>
#include <cstdint>
#include <math.h>

#define BATCH 256
#define SRCLEN 120
#define TGTLEN 24
#define DIN 216
#define HID 1024
#define KPAD 256

#define KC 128                // K per pipeline chunk
#define NCHUNK_H (HID / KC)   // 8
#define NCHUNK_X (KPAD / KC)  // 2
#define NCHUNK (NCHUNK_H + NCHUNK_X)   // 10
#define NSTAGE 2
#define NCTA 128              // persistent grid size (32 x 4)

#define AROW 272              // smem row stride bytes (256B data + 16B pad)
#define OFF_AHI 0
#define OFF_ALO 34816
#define OFF_BHI 69632
#define OFF_BLO 87040
#define STAGE_BYTES 104448
#define SMEM_TOTAL (NSTAGE * STAGE_BYTES)   // 208896

// ---------------------------------------------------------------------------
// Static device scratch (no runtime allocation allowed)
// ---------------------------------------------------------------------------
__device__ __nv_bfloat16 g_Whh_hi[4096 * HID];
__device__ __nv_bfloat16 g_Whh_lo[4096 * HID];
__device__ __nv_bfloat16 g_Wih_hi[4096 * KPAD];
__device__ __nv_bfloat16 g_Wih_lo[4096 * KPAD];
__device__ __nv_bfloat16 g_Xsrc_hi[SRCLEN * BATCH * KPAD];
__device__ __nv_bfloat16 g_Xsrc_lo[SRCLEN * BATCH * KPAD];
__device__ __nv_bfloat16 g_xdec_hi[BATCH * KPAD];
__device__ __nv_bfloat16 g_xdec_lo[BATCH * KPAD];
__device__ __nv_bfloat16 g_hhi[2][BATCH * HID];
__device__ __nv_bfloat16 g_hlo[2][BATCH * HID];
__device__ float g_hf[BATCH * HID];
__device__ float g_c[BATCH * HID];
__device__ float g_bsum[4096];        // b_ih + b_hh pre-summed
__device__ unsigned g_sync_cnt;       // grid-barrier monotonic counter

// ---------------------------------------------------------------------------
// sm_80-safe PTX helpers
// ---------------------------------------------------------------------------
__device__ __forceinline__ uint32_t smem_u32(const void* p) {
    return (uint32_t)__cvta_generic_to_shared(p);
}
__device__ __forceinline__ void cp_async16(uint32_t saddr, const void* gaddr) {
    asm volatile("cp.async.cg.shared.global [%0], [%1], 16;" ::
                 "r"(saddr), "l"(gaddr));
}
__device__ __forceinline__ void cp_commit() {
    asm volatile("cp.async.commit_group;");
}
__device__ __forceinline__ void cp_wait0() {
    asm volatile("cp.async.wait_group 0;");
}
__device__ __forceinline__ void ldmx4(uint32_t addr, uint32_t* r) {
    asm volatile("ldmatrix.sync.aligned.m8n8.x4.shared.b16 {%0,%1,%2,%3}, [%4];"
                 : "=r"(r[0]), "=r"(r[1]), "=r"(r[2]), "=r"(r[3]) : "r"(addr));
}
__device__ __forceinline__ void mma_bf16(float* d, const uint32_t* a,
                                         uint32_t b0, uint32_t b1) {
    asm volatile(
        "mma.sync.aligned.m16n8k16.row.col.f32.bf16.bf16.f32 "
        "{%0,%1,%2,%3}, {%4,%5,%6,%7}, {%8,%9}, {%0,%1,%2,%3};"
        : "+f"(d[0]), "+f"(d[1]), "+f"(d[2]), "+f"(d[3])
        : "r"(a[0]), "r"(a[1]), "r"(a[2]), "r"(a[3]), "r"(b0), "r"(b1));
}

// ===========================================================================
// PERSISTENT ENCODER: 120 LSTM steps in one launch, grid barrier per step.
// CTA tile M=128 ({4 gates} x {32 j}), N=64. Grid (32,4)=128 CTAs (1/SM,
// all co-resident). Cross-boundary A-prefetch hides chunk-0 weight load.
// ===========================================================================
__global__ __launch_bounds__(512) void lstm_encoder_persistent()
{
    extern __shared__ __align__(128) char sm[];
    const uint32_t smb = smem_u32(sm);

    const int tid = threadIdx.x;
    const int wid = tid >> 5;
    const int lane = tid & 31;
    const int j0 = blockIdx.x * 32;
    const int b0 = blockIdx.y * 64;

    const int moff = (wid & 3) * 32;
    const int noff = (wid >> 2) * 16;
    const int rot = ((wid >> 2) + (wid & 3) * 4) & 7;

    // ---- loaders ----
    auto issue_A = [&](int chunk, int stage) {   // weights only (h-independent)
        const __nv_bfloat16 *Ahi, *Alo;
        int ks, k0;
        if (chunk < NCHUNK_H) { Ahi = g_Whh_hi; Alo = g_Whh_lo; ks = HID; k0 = chunk * KC; }
        else { Ahi = g_Wih_hi; Alo = g_Wih_lo; ks = KPAD; k0 = (chunk - NCHUNK_H) * KC; }
        const uint32_t sbase = smb + stage * STAGE_BYTES;
#pragma unroll
        for (int i = 0; i < 8; i++) {
            int o = tid + i * 512;                // 0..4095
            int m = o & 2047;
            int r = m >> 4, c16 = m & 15;
            int grow = ((r >> 5) * HID) + j0 + (r & 31);
            const __nv_bfloat16* g = ((o < 2048) ? Ahi : Alo)
                                     + (size_t)grow * ks + k0 + c16 * 8;
            cp_async16(sbase + ((o < 2048) ? OFF_AHI : OFF_ALO) + r * AROW + c16 * 16, g);
        }
    };
    auto issue_B = [&](int chunk, int stage, int s) {
        const __nv_bfloat16 *Bhi, *Blo;
        int ks, k0;
        if (chunk < NCHUNK_H) {
            Bhi = g_hhi[s & 1]; Blo = g_hlo[s & 1]; ks = HID; k0 = chunk * KC;
        } else {
            Bhi = g_Xsrc_hi + (size_t)s * BATCH * KPAD;
            Blo = g_Xsrc_lo + (size_t)s * BATCH * KPAD;
            ks = KPAD; k0 = (chunk - NCHUNK_H) * KC;
        }
        const uint32_t sbase = smb + stage * STAGE_BYTES;
#pragma unroll
        for (int i = 0; i < 4; i++) {
            int o = tid + i * 512;                // 0..2047
            int mm = o & 1023;
            int r = mm >> 4, c16 = mm & 15;
            const __nv_bfloat16* g = ((o < 1024) ? Bhi : Blo)
                                     + (size_t)(b0 + r) * ks + k0 + c16 * 8;
            cp_async16(sbase + ((o < 1024) ? OFF_BHI : OFF_BLO) + r * AROW + c16 * 16, g);
        }
    };

    float acc0[2][2][4], acc1[2][2][4], acc2[2][2][4];

    auto compute_range = [&](int stage, int g_lo, int g_hi) {
        const uint32_t ab = smb + stage * STAGE_BYTES;
#pragma unroll
        for (int g = g_lo; g < g_hi; g++) {
            const int kk = ((g + rot) & 7) * 16;
            const int col = kk + ((lane >> 4) << 3);
            uint32_t a_hi[2][4], a_lo[2][4];
#pragma unroll
            for (int t = 0; t < 2; t++) {
                int row = moff + t * 16 + (lane & 15);
                ldmx4(ab + OFF_AHI + row * AROW + col * 2, a_hi[t]);
                ldmx4(ab + OFF_ALO + row * AROW + col * 2, a_lo[t]);
            }
            uint32_t b_hi[4], b_lo[4];
            {
                int row = noff + (lane & 15);
                ldmx4(ab + OFF_BHI + row * AROW + col * 2, b_hi);
                ldmx4(ab + OFF_BLO + row * AROW + col * 2, b_lo);
            }
#pragma unroll
            for (int t = 0; t < 2; t++)
#pragma unroll
                for (int q = 0; q < 2; q++) {
                    mma_bf16(acc0[t][q], a_hi[t], b_hi[q], b_hi[q + 2]);
                    mma_bf16(acc1[t][q], a_hi[t], b_lo[q], b_lo[q + 2]);
                    mma_bf16(acc2[t][q], a_lo[t], b_hi[q], b_hi[q + 2]);
                }
        }
    };

    // Dsm in STAGE-1 A region (stage 0 holds the cross-boundary A prefetch)
    float* Dsm = reinterpret_cast<float*>(sm + STAGE_BYTES);

    // prologue: full chunk 0 of step 0
    issue_A(0, 0);
    issue_B(0, 0, 0);
    cp_commit();

    for (int s = 0; s < SRCLEN; s++) {
        __nv_bfloat16* h_hi_out = g_hhi[1 - (s & 1)];
        __nv_bfloat16* h_lo_out = g_hlo[1 - (s & 1)];

#pragma unroll
        for (int t = 0; t < 2; t++)
#pragma unroll
            for (int q = 0; q < 2; q++)
#pragma unroll
                for (int i = 0; i < 4; i++) {
                    acc0[t][q][i] = 0.f; acc1[t][q][i] = 0.f; acc2[t][q][i] = 0.f;
                }

        // mainloop (R15 pattern: wait -> barrier -> 2 groups -> prefetch -> 6)
        for (int i = 0; i < NCHUNK; i++) {
            cp_wait0();
            __syncthreads();
            compute_range(i & 1, 0, 2);
            if (i + 1 < NCHUNK) {
                issue_A(i + 1, (i + 1) & 1);
                issue_B(i + 1, (i + 1) & 1, s);
                cp_commit();
            }
            compute_range(i & 1, 2, 8);
        }

        __syncthreads();                 // drain stage-1 readers (chunk 9)

        // cross-boundary prefetch: next step's chunk-0 WEIGHTS into stage 0
        // (stage-0 readers drained at iter-9 barrier; h not needed yet)
        if (s + 1 < SRCLEN) {
            issue_A(0, 0);
            cp_commit();
        }

        // epilogue: frags -> Dsm (stage 1) -> pointwise
#pragma unroll
        for (int t = 0; t < 2; t++)
#pragma unroll
            for (int q = 0; q < 2; q++) {
                int r0 = moff + t * 16 + (lane >> 2);
                int c0 = noff + q * 8 + (lane & 3) * 2;
#pragma unroll
                for (int i = 0; i < 4; i++) {
                    float v = acc0[t][q][i] + acc1[t][q][i] + acc2[t][q][i];
                    Dsm[(r0 + (i >> 1) * 8) * 68 + c0 + (i & 1)] = v;
                }
            }
        __syncthreads();

#pragma unroll
        for (int i = 0; i < 4; i++) {
            int id = tid + i * 512;
            int bb = id >> 5;
            int jj = id & 31;
            int b = b0 + bb;
            int jg = j0 + jj;
            float gi = Dsm[(0  + jj) * 68 + bb] + g_bsum[jg];
            float gf = Dsm[(32 + jj) * 68 + bb] + g_bsum[HID + jg];
            float gg = Dsm[(64 + jj) * 68 + bb] + g_bsum[2*HID + jg];
            float go = Dsm[(96 + jj) * 68 + bb] + g_bsum[3*HID + jg];
            float iv = 1.f / (1.f + expf(-gi));
            float fv = 1.f / (1.f + expf(-gf));
            float gv = tanhf(gg);
            float ov = 1.f / (1.f + expf(-go));
            size_t idx = (size_t)b * HID + jg;
            float cn = fv * g_c[idx] + iv * gv;
            g_c[idx] = cn;
            float hv = ov * tanhf(cn);
            __nv_bfloat16 hh = __float2bfloat16(hv);
            h_hi_out[idx] = hh;
            h_lo_out[idx] = __float2bfloat16(hv - __bfloat162float(hh));
        }

        // grid barrier: publish h before any CTA loads it for step s+1
        if (s + 1 < SRCLEN) {
            if (tid == 0) {
                __threadfence();
                atomicAdd(&g_sync_cnt, 1u);
                const unsigned target = (unsigned)NCTA * (unsigned)(s + 1);
                while (atomicAdd(&g_sync_cnt, 0u) < target) {}
                __threadfence();
            }
            __syncthreads();
            issue_B(0, 0, s + 1);        // new h rows into stage 0
            cp_commit();
        }
    }
}

// ---------------------------------------------------------------------------
// Decoder step kernel (R15, unchanged semantics)
// ---------------------------------------------------------------------------
__global__ __launch_bounds__(512) void lstm_mma_step(
    const __nv_bfloat16* __restrict__ x_hi, const __nv_bfloat16* __restrict__ x_lo,
    const __nv_bfloat16* __restrict__ h_hi_in, const __nv_bfloat16* __restrict__ h_lo_in,
    float* __restrict__ h_out,
    __nv_bfloat16* __restrict__ h_hi_out, __nv_bfloat16* __restrict__ h_lo_out,
    float* __restrict__ c)
{
    extern __shared__ __align__(128) char sm[];
    const uint32_t smb = smem_u32(sm);

    const int tid = threadIdx.x;
    const int wid = tid >> 5;
    const int lane = tid & 31;
    const int j0 = blockIdx.x * 32;
    const int b0 = blockIdx.y * 64;

    const int moff = (wid & 3) * 32;
    const int noff = (wid >> 2) * 16;
    const int rot = ((wid >> 2) + (wid & 3) * 4) & 7;

    float acc0[2][2][4], acc1[2][2][4], acc2[2][2][4];
#pragma unroll
    for (int t = 0; t < 2; t++)
#pragma unroll
        for (int q = 0; q < 2; q++)
#pragma unroll
            for (int i = 0; i < 4; i++) {
                acc0[t][q][i] = 0.f; acc1[t][q][i] = 0.f; acc2[t][q][i] = 0.f;
            }

    auto issue_loads = [&](int chunk, int stage) {
        const __nv_bfloat16 *Ahi, *Alo, *Bhi, *Blo;
        int ks, k0;
        if (chunk < NCHUNK_H) {
            Ahi = g_Whh_hi; Alo = g_Whh_lo; Bhi = h_hi_in; Blo = h_lo_in;
            ks = HID; k0 = chunk * KC;
        } else {
            Ahi = g_Wih_hi; Alo = g_Wih_lo; Bhi = x_hi; Blo = x_lo;
            ks = KPAD; k0 = (chunk - NCHUNK_H) * KC;
        }
        const uint32_t sbase = smb + stage * STAGE_BYTES;
#pragma unroll
        for (int i = 0; i < 12; i++) {
            int o = tid + i * 512;
            const __nv_bfloat16* g;
            uint32_t soff;
            if (o < 4096) {
                int m = o & 2047;
                int r = m >> 4, c16 = m & 15;
                int grow = ((r >> 5) * HID) + j0 + (r & 31);
                g = ((o < 2048) ? Ahi : Alo) + (size_t)grow * ks + k0 + c16 * 8;
                soff = ((o < 2048) ? OFF_AHI : OFF_ALO) + r * AROW + c16 * 16;
            } else {
                int m = o - 4096;
                int mm = m & 1023;
                int r = mm >> 4, c16 = mm & 15;
                g = ((m < 1024) ? Bhi : Blo) + (size_t)(b0 + r) * ks + k0 + c16 * 8;
                soff = ((m < 1024) ? OFF_BHI : OFF_BLO) + r * AROW + c16 * 16;
            }
            cp_async16(sbase + soff, g);
        }
        cp_commit();
    };

    auto compute_range = [&](int stage, int g_lo, int g_hi) {
        const uint32_t ab = smb + stage * STAGE_BYTES;
#pragma unroll
        for (int g = g_lo; g < g_hi; g++) {
            const int kk = ((g + rot) & 7) * 16;
            const int col = kk + ((lane >> 4) << 3);
            uint32_t a_hi[2][4], a_lo[2][4];
#pragma unroll
            for (int t = 0; t < 2; t++) {
                int row = moff + t * 16 + (lane & 15);
                ldmx4(ab + OFF_AHI + row * AROW + col * 2, a_hi[t]);
                ldmx4(ab + OFF_ALO + row * AROW + col * 2, a_lo[t]);
            }
            uint32_t b_hi[4], b_lo[4];
            {
                int row = noff + (lane & 15);
                ldmx4(ab + OFF_BHI + row * AROW + col * 2, b_hi);
                ldmx4(ab + OFF_BLO + row * AROW + col * 2, b_lo);
            }
#pragma unroll
            for (int t = 0; t < 2; t++)
#pragma unroll
                for (int q = 0; q < 2; q++) {
                    mma_bf16(acc0[t][q], a_hi[t], b_hi[q], b_hi[q + 2]);
                    mma_bf16(acc1[t][q], a_hi[t], b_lo[q], b_lo[q + 2]);
                    mma_bf16(acc2[t][q], a_lo[t], b_hi[q], b_hi[q + 2]);
                }
        }
    };

    issue_loads(0, 0);
    for (int i = 0; i < NCHUNK; i++) {
        cp_wait0();
        __syncthreads();
        compute_range(i & 1, 0, 2);
        if (i + 1 < NCHUNK) issue_loads(i + 1, (i + 1) & 1);
        compute_range(i & 1, 2, 8);
    }

    float* Dsm = reinterpret_cast<float*>(sm);
#pragma unroll
    for (int t = 0; t < 2; t++)
#pragma unroll
        for (int q = 0; q < 2; q++) {
            int r0 = moff + t * 16 + (lane >> 2);
            int c0 = noff + q * 8 + (lane & 3) * 2;
#pragma unroll
            for (int i = 0; i < 4; i++) {
                float v = acc0[t][q][i] + acc1[t][q][i] + acc2[t][q][i];
                Dsm[(r0 + (i >> 1) * 8) * 68 + c0 + (i & 1)] = v;
            }
        }
    __syncthreads();

#pragma unroll
    for (int i = 0; i < 4; i++) {
        int id = tid + i * 512;
        int bb = id >> 5;
        int jj = id & 31;
        int b = b0 + bb;
        int jg = j0 + jj;
        float gi = Dsm[(0  + jj) * 68 + bb] + g_bsum[jg];
        float gf = Dsm[(32 + jj) * 68 + bb] + g_bsum[HID + jg];
        float gg = Dsm[(64 + jj) * 68 + bb] + g_bsum[2*HID + jg];
        float go = Dsm[(96 + jj) * 68 + bb] + g_bsum[3*HID + jg];
        float iv = 1.f / (1.f + expf(-gi));
        float fv = 1.f / (1.f + expf(-gf));
        float gv = tanhf(gg);
        float ov = 1.f / (1.f + expf(-go));
        size_t idx = (size_t)b * HID + jg;
        float cn = fv * c[idx] + iv * gv;
        c[idx] = cn;
        float hv = ov * tanhf(cn);
        if (h_out) h_out[idx] = hv;
        __nv_bfloat16 hh = __float2bfloat16(hv);
        h_hi_out[idx] = hh;
        h_lo_out[idx] = __float2bfloat16(hv - __bfloat162float(hh));
    }
}

// ---------------------------------------------------------------------------
// Conversion kernels
// ---------------------------------------------------------------------------
__global__ void split_mat_kernel(const float* __restrict__ src,
                                 __nv_bfloat16* __restrict__ hi,
                                 __nv_bfloat16* __restrict__ lo, int n) {
    int i = blockIdx.x * blockDim.x + threadIdx.x;
    if (i < n) {
        float v = src[i];
        __nv_bfloat16 h = __float2bfloat16(v);
        hi[i] = h;
        lo[i] = __float2bfloat16(v - __bfloat162float(h));
    }
}

__global__ void split_pad_kernel(const float* __restrict__ src, int srcStride, int srcK,
                                 __nv_bfloat16* __restrict__ hi,
                                 __nv_bfloat16* __restrict__ lo, int rows, int dstK) {
    int i = blockIdx.x * blockDim.x + threadIdx.x;
    if (i < rows * dstK) {
        int r = i / dstK, k = i % dstK;
        float v = (k < srcK) ? src[(size_t)r * srcStride + k] : 0.f;
        __nv_bfloat16 h = __float2bfloat16(v);
        hi[i] = h;
        lo[i] = __float2bfloat16(v - __bfloat162float(h));
    }
}

__global__ void split_src_kernel(const float* __restrict__ src,
                                 __nv_bfloat16* __restrict__ hi,
                                 __nv_bfloat16* __restrict__ lo) {
    int i = blockIdx.x * blockDim.x + threadIdx.x;
    if (i < SRCLEN * BATCH * KPAD) {
        int k = i & (KPAD - 1);
        int sb = i >> 8;
        int b = sb & (BATCH - 1);
        int s = sb >> 8;
        float v = (k < DIN) ? src[((size_t)b * SRCLEN + s) * DIN + k] : 0.f;
        __nv_bfloat16 h = __float2bfloat16(v);
        hi[i] = h;
        lo[i] = __float2bfloat16(v - __bfloat162float(h));
    }
}

__global__ void bias_sum_kernel(const float* __restrict__ b_ih,
                                const float* __restrict__ b_hh,
                                float* __restrict__ bsum) {
    int i = blockIdx.x * blockDim.x + threadIdx.x;
    if (i < 4096) bsum[i] = b_ih[i] + b_hh[i];
}

// ---------------------------------------------------------------------------
// Output projection fused with feedback split
// ---------------------------------------------------------------------------
__global__ __launch_bounds__(256) void out_proj_kernel(
    const float* __restrict__ h,
    const float* __restrict__ W_out,
    const float* __restrict__ b_out,
    float* __restrict__ out, int out_stride,
    __nv_bfloat16* __restrict__ xd_hi, __nv_bfloat16* __restrict__ xd_lo)
{
    __shared__ float Hs[16][17];
    __shared__ float Wo[16][17];

    const int tid = threadIdx.x;
    const int txd = tid & 15;
    const int tyb = tid >> 4;
    const int d0 = blockIdx.x * 16;
    const int b0 = blockIdx.y * 16;

    float acc = 0.f;
    for (int k0 = 0; k0 < HID; k0 += 16) {
        __syncthreads();
        Hs[txd][tyb] = h[(size_t)(b0 + tyb) * HID + k0 + txd];
        Wo[txd][tyb] = (d0 + tyb < DIN)
            ? W_out[(size_t)(d0 + tyb) * HID + k0 + txd] : 0.f;
        __syncthreads();
#pragma unroll
        for (int k = 0; k < 16; k++)
            acc += Hs[k][tyb] * Wo[k][txd];
    }
    if (d0 + txd < DIN) {
        float v = acc + b_out[d0 + txd];
        out[(size_t)(b0 + tyb) * out_stride + d0 + txd] = v;
        if (xd_hi) {
            size_t xi = (size_t)(b0 + tyb) * KPAD + d0 + txd;
            __nv_bfloat16 hh = __float2bfloat16(v);
            xd_hi[xi] = hh;
            xd_lo[xi] = __float2bfloat16(v - __bfloat162float(hh));
        }
    }
}

// ---------------------------------------------------------------------------
extern "C" void kernel_launch(void* const* d_in, const int* in_sizes, int n_in,
                              void* d_out, int out_size)
{
    const float* src   = (const float*)d_in[0];
    const float* W_ih  = (const float*)d_in[2];
    const float* W_hh  = (const float*)d_in[3];
    const float* b_ih  = (const float*)d_in[4];
    const float* b_hh  = (const float*)d_in[5];
    const float* W_out = (const float*)d_in[6];
    const float* b_out = (const float*)d_in[7];
    float* out = (float*)d_out;

    static bool attr_set = false;
    if (!attr_set) {
        cudaFuncSetAttribute(lstm_mma_step,
                             cudaFuncAttributeMaxDynamicSharedMemorySize, SMEM_TOTAL);
        cudaFuncSetAttribute(lstm_encoder_persistent,
                             cudaFuncAttributeMaxDynamicSharedMemorySize, SMEM_TOTAL);
        attr_set = true;
    }

    __nv_bfloat16 *Whh_hi, *Wih_hi, *Xs_hi, *Xs_lo, *xd_hi, *xd_lo, *hhi, *hlo;
    __nv_bfloat16 *Whh_lo, *Wih_lo;
    float *hf, *cc, *bsum;
    unsigned* sync_cnt;
    cudaGetSymbolAddress((void**)&Whh_hi, g_Whh_hi);
    cudaGetSymbolAddress((void**)&Whh_lo, g_Whh_lo);
    cudaGetSymbolAddress((void**)&Wih_hi, g_Wih_hi);
    cudaGetSymbolAddress((void**)&Wih_lo, g_Wih_lo);
    cudaGetSymbolAddress((void**)&Xs_hi, g_Xsrc_hi);
    cudaGetSymbolAddress((void**)&Xs_lo, g_Xsrc_lo);
    cudaGetSymbolAddress((void**)&xd_hi, g_xdec_hi);
    cudaGetSymbolAddress((void**)&xd_lo, g_xdec_lo);
    cudaGetSymbolAddress((void**)&hhi, g_hhi);
    cudaGetSymbolAddress((void**)&hlo, g_hlo);
    cudaGetSymbolAddress((void**)&hf, g_hf);
    cudaGetSymbolAddress((void**)&cc, g_c);
    cudaGetSymbolAddress((void**)&bsum, g_bsum);
    cudaGetSymbolAddress((void**)&sync_cnt, g_sync_cnt);
    __nv_bfloat16* hhb[2] = {hhi, hhi + BATCH * HID};
    __nv_bfloat16* hlb[2] = {hlo, hlo + BATCH * HID};

    cudaMemsetAsync(hhb[0], 0, (size_t)BATCH * HID * sizeof(__nv_bfloat16));
    cudaMemsetAsync(hlb[0], 0, (size_t)BATCH * HID * sizeof(__nv_bfloat16));
    cudaMemsetAsync(cc, 0, (size_t)BATCH * HID * sizeof(float));
    cudaMemsetAsync(xd_hi, 0, (size_t)BATCH * KPAD * sizeof(__nv_bfloat16));
    cudaMemsetAsync(xd_lo, 0, (size_t)BATCH * KPAD * sizeof(__nv_bfloat16));
    cudaMemsetAsync(sync_cnt, 0, sizeof(unsigned));

    {
        int n = 4096 * HID;
        split_mat_kernel<<<(n + 255) / 256, 256>>>(W_hh, Whh_hi, Whh_lo, n);
        split_pad_kernel<<<(4096 * KPAD + 255) / 256, 256>>>(W_ih, DIN, DIN,
                                                             Wih_hi, Wih_lo, 4096, KPAD);
        int m = SRCLEN * BATCH * KPAD;
        split_src_kernel<<<(m + 255) / 256, 256>>>(src, Xs_hi, Xs_lo);
        bias_sum_kernel<<<16, 256>>>(b_ih, b_hh, bsum);
    }

    dim3 grid(32, 4);
    dim3 pgrid(14, 16);

    // Encoder: one persistent launch, 120 steps with internal grid barriers
    lstm_encoder_persistent<<<grid, 512, SMEM_TOTAL>>>();
    int cur = 0;   // after 120 steps, h lives in buffer 0

    // Decoder
    const __nv_bfloat16* x_hi = Xs_hi + (size_t)(SRCLEN - 1) * BATCH * KPAD;
    const __nv_bfloat16* x_lo = Xs_lo + (size_t)(SRCLEN - 1) * BATCH * KPAD;
    for (int t = 0; t < TGTLEN; t++) {
        lstm_mma_step<<<grid, 512, SMEM_TOTAL>>>(
            x_hi, x_lo, hhb[cur], hlb[cur], hf, hhb[1 - cur], hlb[1 - cur], cc);
        cur ^= 1;
        bool feed = (t + 1 < TGTLEN);
        out_proj_kernel<<<pgrid, 256>>>(hf, W_out, b_out,
                                        out + (size_t)t * DIN, TGTLEN * DIN,
                                        feed ? xd_hi : nullptr,
                                        feed ? xd_lo : nullptr);
        x_hi = xd_hi;
        x_lo = xd_lo;
    }
}